// round 12
// baseline (speedup 1.0000x reference)
#include <cuda_runtime.h>
#include <math.h>

#define BATCH 128
#define NN 256
#define EMB 256
#define LD 512
#define TST 256
#define G4 2048

// ---------------- scratch (device globals; no allocations) ------------------
__device__ float g_G[(size_t)BATCH*2*NN*EMB];     // embedded g1|g2
__device__ float g_S[(size_t)BATCH*NN*NN];        // similarity [b][t][n]
__device__ float g_XP[(size_t)TST*BATCH*G4];      // [s][b][r] xt@W_ih^T + biases
__device__ float g_HS[(size_t)TST*BATCH*LD];      // [s][b][j] all h_t
__device__ float g_K[(size_t)TST*BATCH*NN];       // [t][b][n] exp(M)
__device__ float g_u[BATCH*NN];
__device__ float g_v[BATCH*NN];
__device__ float g_Wr[G4*LD];                     // W_hh reordered (rows 4j+gate)
__device__ float g_Wi[G4*NN];                     // W_ih reordered
__device__ float g_br[G4];                        // b_ih+b_hh reordered
__device__ unsigned g_barctr4[4*32];              // per-bg barrier counters

// ---------------- packed f32x2 helpers --------------------------------------
__device__ __forceinline__ unsigned long long pk2(float lo, float hi) {
    unsigned long long r;
    asm("mov.b64 %0, {%1, %2};" : "=l"(r) : "f"(lo), "f"(hi));
    return r;
}
__device__ __forceinline__ void upk2(unsigned long long v, float &lo, float &hi) {
    asm("mov.b64 {%0, %1}, %2;" : "=f"(lo), "=f"(hi) : "l"(v));
}
__device__ __forceinline__ void fma2(unsigned long long &d, unsigned long long a,
                                     unsigned long long b) {
    asm("fma.rn.f32x2 %0, %1, %2, %0;" : "+l"(d) : "l"(a), "l"(b));
}
__device__ __forceinline__ void add2(unsigned long long &d, unsigned long long a) {
    asm("add.rn.f32x2 %0, %0, %1;" : "+l"(d) : "l"(a));
}

__device__ __forceinline__ float fsig(float x) {
    return 1.f / (1.f + __expf(-x));
}
__device__ __forceinline__ float ftanh(float x) {
    return 1.f - 2.f / (1.f + __expf(2.f * x));
}

// ---------------- init: barrier ctrs; v = 1 ---------------------------------
__global__ void init_k() {
    int i = blockIdx.x * 256 + threadIdx.x;
    if (i < BATCH * NN) g_v[i] = 1.f;
    if (i < 128) g_barctr4[i] = 0u;
}

// ---------------- reorder W_hh/W_ih rows to 4j+gate; combine biases ---------
__global__ void reorder_k(const float* __restrict__ W_ih,
                          const float* __restrict__ W_hh,
                          const float* __restrict__ b_ih,
                          const float* __restrict__ b_hh) {
    int idx = blockIdx.x * 256 + threadIdx.x;    // G4*LD = 1048576
    int R = idx >> 9, k = idx & 511;
    int j = R >> 2, gt = R & 3;
    int src = gt * 512 + j;
    g_Wr[(size_t)R * LD + k] = W_hh[(size_t)src * LD + k];
    if (k < NN) g_Wi[(size_t)R * NN + k] = W_ih[(size_t)src * NN + k];
    if (k == 0) g_br[R] = b_ih[src] + b_hh[src];
}

// ---------------- embedding + leaky relu ------------------------------------
__global__ void __launch_bounds__(256) embed_kernel(
    const float* __restrict__ x, const float* __restrict__ W_emb,
    const float* __restrict__ b_emb)
{
    __shared__ float sW[32 * 256];
    __shared__ float sx[16 * 32];
    int tid = threadIdx.x;
    int b = blockIdx.y;
    int p0 = blockIdx.x * 16;
    for (int idx = tid; idx < 256 * 32; idx += 256) {
        int e = idx >> 5, f = idx & 31;
        sW[f * 256 + e] = W_emb[idx];
    }
    for (int idx = tid; idx < 512; idx += 256)
        sx[idx] = x[((size_t)b * 512 + p0) * 32 + idx];
    __syncthreads();
    int e = tid;
    float bias = b_emb[e];
    float acc[16];
#pragma unroll
    for (int r = 0; r < 16; ++r) acc[r] = bias;
#pragma unroll
    for (int f = 0; f < 32; ++f) {
        float w = sW[f * 256 + e];
#pragma unroll
        for (int r = 0; r < 16; ++r) acc[r] += sx[r * 32 + f] * w;
    }
#pragma unroll
    for (int r = 0; r < 16; ++r) {
        float v = acc[r];
        v = (v > 0.f) ? v : 0.01f * v;
        g_G[((size_t)b * 512 + p0 + r) * 256 + e] = v;
    }
}

// ---------------- gemm128 v3: duplicated-A smem (no pk2 in hot loop) --------
// C[m,n]=sum_k A[m,k]B[n,k]; 128x128 tile, 256 threads, 8x8 microtile, f32x2.
// A stored in smem as (a,a) pairs -> direct LDS.128 of packed operands.
// MODE 0: plain   MODE 1: +bias[n]   MODE 2: __expf(acc + bias[n])
template <int MODE>
__global__ void __launch_bounds__(256, 2) gemm128(
    const float* __restrict__ A, int ldA, size_t Abat, size_t Astep,
    const float* __restrict__ B, int ldB, size_t Bbat,
    const float* __restrict__ bias,
    float* __restrict__ C, int ldC, size_t Cbat, int K)
{
    __shared__ __align__(16) float Asd[2][16 * 256];   // duplicated pairs
    __shared__ __align__(16) float Bs[2][16 * 128];
    int tid = threadIdx.x;
    int tx = tid & 15, ty = tid >> 4;
    size_t zo = blockIdx.z;
    A += zo * Abat + (size_t)blockIdx.y * Astep;
    B += zo * Bbat + (size_t)blockIdx.x * 128 * ldB;
    C += zo * Cbat + (size_t)blockIdx.y * 128 * ldC + (size_t)blockIdx.x * 128;

    int lrow = tid >> 1, lkq = (tid & 1) * 8;
    const float* Ald = A + (size_t)lrow * ldA + lkq;
    const float* Bld = B + (size_t)lrow * ldB + lkq;

    unsigned long long acc[8][4];
#pragma unroll
    for (int i = 0; i < 8; ++i)
#pragma unroll
        for (int j = 0; j < 4; ++j) acc[i][j] = 0ULL;

#define ST_TILE(BUF, AV0, AV1, BV0, BV1) do {                                  \
    unsigned long long _pp;                                                    \
    _pp = pk2((AV0).x, (AV0).x);                                               \
    *(unsigned long long*)&Asd[BUF][(lkq + 0) * 256 + 2 * lrow] = _pp;         \
    _pp = pk2((AV0).y, (AV0).y);                                               \
    *(unsigned long long*)&Asd[BUF][(lkq + 1) * 256 + 2 * lrow] = _pp;         \
    _pp = pk2((AV0).z, (AV0).z);                                               \
    *(unsigned long long*)&Asd[BUF][(lkq + 2) * 256 + 2 * lrow] = _pp;         \
    _pp = pk2((AV0).w, (AV0).w);                                               \
    *(unsigned long long*)&Asd[BUF][(lkq + 3) * 256 + 2 * lrow] = _pp;         \
    _pp = pk2((AV1).x, (AV1).x);                                               \
    *(unsigned long long*)&Asd[BUF][(lkq + 4) * 256 + 2 * lrow] = _pp;         \
    _pp = pk2((AV1).y, (AV1).y);                                               \
    *(unsigned long long*)&Asd[BUF][(lkq + 5) * 256 + 2 * lrow] = _pp;         \
    _pp = pk2((AV1).z, (AV1).z);                                               \
    *(unsigned long long*)&Asd[BUF][(lkq + 6) * 256 + 2 * lrow] = _pp;         \
    _pp = pk2((AV1).w, (AV1).w);                                               \
    *(unsigned long long*)&Asd[BUF][(lkq + 7) * 256 + 2 * lrow] = _pp;         \
    Bs[BUF][(lkq + 0) * 128 + lrow] = (BV0).x;                                 \
    Bs[BUF][(lkq + 1) * 128 + lrow] = (BV0).y;                                 \
    Bs[BUF][(lkq + 2) * 128 + lrow] = (BV0).z;                                 \
    Bs[BUF][(lkq + 3) * 128 + lrow] = (BV0).w;                                 \
    Bs[BUF][(lkq + 4) * 128 + lrow] = (BV1).x;                                 \
    Bs[BUF][(lkq + 5) * 128 + lrow] = (BV1).y;                                 \
    Bs[BUF][(lkq + 6) * 128 + lrow] = (BV1).z;                                 \
    Bs[BUF][(lkq + 7) * 128 + lrow] = (BV1).w;                                 \
} while (0)

    float4 av0 = *(const float4*)(Ald);
    float4 av1 = *(const float4*)(Ald + 4);
    float4 bv0 = *(const float4*)(Bld);
    float4 bv1 = *(const float4*)(Bld + 4);
    ST_TILE(0, av0, av1, bv0, bv1);
    __syncthreads();

    int NT = K >> 4;
    int p = 0;
    for (int it = 0; it < NT; ++it) {
        if (it + 1 < NT) {
            int kt = (it + 1) << 4;
            av0 = *(const float4*)(Ald + kt);
            av1 = *(const float4*)(Ald + kt + 4);
            bv0 = *(const float4*)(Bld + kt);
            bv1 = *(const float4*)(Bld + kt + 4);
        }
        const float* Ap = Asd[p];
        const float* Bp = Bs[p];
#pragma unroll
        for (int kk = 0; kk < 16; ++kk) {
            ulonglong2 a01 = *(const ulonglong2*)&Ap[kk * 256 + ty * 8];
            ulonglong2 a23 = *(const ulonglong2*)&Ap[kk * 256 + ty * 8 + 4];
            ulonglong2 a45 = *(const ulonglong2*)&Ap[kk * 256 + 128 + ty * 8];
            ulonglong2 a67 = *(const ulonglong2*)&Ap[kk * 256 + 128 + ty * 8 + 4];
            ulonglong2 b0 = *(const ulonglong2*)&Bp[kk * 128 + tx * 4];
            ulonglong2 b1 = *(const ulonglong2*)&Bp[kk * 128 + 64 + tx * 4];
            fma2(acc[0][0], a01.x, b0.x); fma2(acc[0][1], a01.x, b0.y);
            fma2(acc[0][2], a01.x, b1.x); fma2(acc[0][3], a01.x, b1.y);
            fma2(acc[1][0], a01.y, b0.x); fma2(acc[1][1], a01.y, b0.y);
            fma2(acc[1][2], a01.y, b1.x); fma2(acc[1][3], a01.y, b1.y);
            fma2(acc[2][0], a23.x, b0.x); fma2(acc[2][1], a23.x, b0.y);
            fma2(acc[2][2], a23.x, b1.x); fma2(acc[2][3], a23.x, b1.y);
            fma2(acc[3][0], a23.y, b0.x); fma2(acc[3][1], a23.y, b0.y);
            fma2(acc[3][2], a23.y, b1.x); fma2(acc[3][3], a23.y, b1.y);
            fma2(acc[4][0], a45.x, b0.x); fma2(acc[4][1], a45.x, b0.y);
            fma2(acc[4][2], a45.x, b1.x); fma2(acc[4][3], a45.x, b1.y);
            fma2(acc[5][0], a45.y, b0.x); fma2(acc[5][1], a45.y, b0.y);
            fma2(acc[5][2], a45.y, b1.x); fma2(acc[5][3], a45.y, b1.y);
            fma2(acc[6][0], a67.x, b0.x); fma2(acc[6][1], a67.x, b0.y);
            fma2(acc[6][2], a67.x, b1.x); fma2(acc[6][3], a67.x, b1.y);
            fma2(acc[7][0], a67.y, b0.x); fma2(acc[7][1], a67.y, b0.y);
            fma2(acc[7][2], a67.y, b1.x); fma2(acc[7][3], a67.y, b1.y);
        }
        if (it + 1 < NT) {
            int q = p ^ 1;
            ST_TILE(q, av0, av1, bv0, bv1);
        }
        __syncthreads();
        p ^= 1;
    }
#undef ST_TILE

    int nb0 = blockIdx.x * 128 + tx * 4;
#pragma unroll
    for (int i = 0; i < 8; ++i) {
        int m = (i < 4) ? (ty * 4 + i) : (64 + ty * 4 + (i - 4));
#pragma unroll
        for (int half = 0; half < 2; ++half) {
            float r0, r1, r2, r3;
            upk2(acc[i][half * 2 + 0], r0, r1);
            upk2(acc[i][half * 2 + 1], r2, r3);
            int nb = nb0 + half * 64;
            if (MODE == 1) {
                r0 += bias[nb + 0]; r1 += bias[nb + 1];
                r2 += bias[nb + 2]; r3 += bias[nb + 3];
            }
            if (MODE == 2) {
                r0 = __expf(r0 + bias[nb + 0]); r1 = __expf(r1 + bias[nb + 1]);
                r2 = __expf(r2 + bias[nb + 2]); r3 = __expf(r3 + bias[nb + 3]);
            }
            float4 o; o.x = r0; o.y = r1; o.z = r2; o.w = r3;
            *(float4*)(C + (size_t)m * ldC + tx * 4 + half * 64) = o;
        }
    }
}

// ---------------- persistent fused LSTM v5 (k-chunk staged pipeline) --------
// 128 blocks x 256 threads. Block (rg=bid&31, bg=bid>>5): gate-rows
// [rg*64,+64) (hidden [rg*16,+16)), batches [bg*32,+32).
// k split into 4 chunks of 128; H chunk c+1 staged (LDG early, STS late) while
// chunk c is FMA'd from the other buffer. Warp w owns k {c*128+w*16..+15}.
// W smem-resident with per-8-row pad; partials [warp][b*68+r]; per-bg barrier.
#define HS_CH 132
#define PSTR 68
#define WSZ (64 * 516 + 32)
#define PART_OFF WSZ
#define PART_SZ (8 * 32 * PSTR)        /* 17408 >= 2 chunk buffers (8448) */
#define LSTM_SMEM ((WSZ + PART_SZ) * 4)

__device__ __forceinline__ int woff(int r) { return r * 516 + ((r >> 3) << 2); }

__global__ void __launch_bounds__(256, 1) lstm_persist(
    const float* __restrict__ XP, const float* __restrict__ Wr,
    float* __restrict__ HS)
{
    extern __shared__ float sm[];
    float* Ws = sm;
    float* Hbuf0 = sm + PART_OFF;          // 32 x 132
    float* Hbuf1 = Hbuf0 + 32 * HS_CH;     // 32 x 132
    float* part = sm + PART_OFF;           // aliases H buffers (used after GEMM)

    int tid = threadIdx.x;
    int rg = blockIdx.x & 31;
    int bg = blockIdx.x >> 5;
    int warp = tid >> 5;
    int lane = tid & 31;
    int bq = lane & 3;
    int rq = (lane >> 2) & 7;
    int wk16 = warp * 16;                  // warp's k offset within a chunk

    // load W slice once (64 rows x 512) with per-8-row pad
    for (int i = tid; i < 64 * 128; i += 256) {
        int r = i >> 7, kq = (i & 127) * 4;
        float4 v = *(const float4*)&Wr[(size_t)(rg * 64 + r) * LD + kq];
        *(float4*)&Ws[woff(r) + kq] = v;
    }

    int bl = tid & 31;
    int h0 = tid >> 5;                     // 0..7 ; pair handles h0 and h0+8
    int bgl = bg * 32 + bl;
    int jg0 = rg * 16 + h0, jg1 = jg0 + 8;
    float c0 = 0.f, c1 = 0.f;
    unsigned* ctr = &g_barctr4[bg * 32];
    int wbase = rq * 516;                  // row rq+8j at rq*516 + j*4132

    __syncthreads();

    for (int s = 0; s < TST; ++s) {
        // XP gate prefetch (time-major slab)
        const float* xpr = &XP[((size_t)s * BATCH + bgl) * G4 + rg * 64];
        float4 g0 = *(const float4*)&xpr[4 * h0];
        float4 g1v = *(const float4*)&xpr[4 * h0 + 32];

        if (s > 0) {
            const float* Hsrc = HS + ((size_t)(s - 1) * BATCH + bg * 32) * LD;

            // stage chunk 0
#pragma unroll
            for (int j = 0; j < 4; ++j) {
                int i = tid + j * 256;
                int b = i >> 5, kq = (i & 31) * 4;
                float4 v = *(const float4*)&Hsrc[(size_t)b * LD + kq];
                *(float4*)&Hbuf0[b * HS_CH + kq] = v;
            }
            __syncthreads();

            unsigned long long acc[8][8];
#pragma unroll
            for (int i = 0; i < 8; ++i)
#pragma unroll
                for (int j = 0; j < 8; ++j) acc[i][j] = 0ULL;

#pragma unroll 1
            for (int c = 0; c < 4; ++c) {
                // issue next chunk's global loads first (latency overlap)
                float4 st[4];
                if (c < 3) {
#pragma unroll
                    for (int j = 0; j < 4; ++j) {
                        int i = tid + j * 256;
                        int b = i >> 5, kq = (i & 31) * 4;
                        st[j] = *(const float4*)
                            &Hsrc[(size_t)b * LD + (c + 1) * 128 + kq];
                    }
                }
                const float* Hc = (c & 1) ? Hbuf1 : Hbuf0;
                int kc = c * 128 + wk16;
#pragma unroll
                for (int q = 0; q < 4; ++q) {
                    int k4 = q * 4;
                    ulonglong2 h4[8], w4[8];
#pragma unroll
                    for (int i = 0; i < 8; ++i)
                        h4[i] = *(const ulonglong2*)
                            &Hc[(bq + 4 * i) * HS_CH + wk16 + k4];
#pragma unroll
                    for (int j = 0; j < 8; ++j)
                        w4[j] = *(const ulonglong2*)
                            &Ws[wbase + j * 4132 + kc + k4];
#pragma unroll
                    for (int i = 0; i < 8; ++i)
#pragma unroll
                        for (int j = 0; j < 8; ++j) {
                            fma2(acc[i][j], h4[i].x, w4[j].x);
                            fma2(acc[i][j], h4[i].y, w4[j].y);
                        }
                }
                if (c < 3) {
                    float* Hn = ((c + 1) & 1) ? Hbuf1 : Hbuf0;
#pragma unroll
                    for (int j = 0; j < 4; ++j) {
                        int i = tid + j * 256;
                        int b = i >> 5, kq = (i & 31) * 4;
                        *(float4*)&Hn[b * HS_CH + kq] = st[j];
                    }
                }
                __syncthreads();
            }

            // partials: part[warp][b*68 + r], r = rq+8j
            float* pw = part + warp * (32 * PSTR);
#pragma unroll
            for (int i = 0; i < 8; ++i) {
                float* pb = pw + (bq + 4 * i) * PSTR + rq;
#pragma unroll
                for (int j = 0; j < 8; ++j) {
                    float lo, hi; upk2(acc[i][j], lo, hi);
                    pb[8 * j] = lo + hi;
                }
            }
            __syncthreads();

            // reduce 8 warps: LDS.128 + packed adds
            ulonglong2 A0 = *(ulonglong2*)&g0;
            ulonglong2 A1 = *(ulonglong2*)&g1v;
#pragma unroll
            for (int w = 0; w < 8; ++w) {
                const float* pr = part + w * (32 * PSTR) + bl * PSTR;
                ulonglong2 qa = *(const ulonglong2*)&pr[4 * h0];
                ulonglong2 qb = *(const ulonglong2*)&pr[4 * h0 + 32];
                add2(A0.x, qa.x); add2(A0.y, qa.y);
                add2(A1.x, qb.x); add2(A1.y, qb.y);
            }
            *(ulonglong2*)&g0 = A0;
            *(ulonglong2*)&g1v = A1;
        }

        // gate order per hidden unit: [i, f, g, o]
        float* Hdst = &HS[((size_t)s * BATCH + bgl) * LD];
        {
            float i_ = fsig(g0.x), f_ = fsig(g0.y);
            float gg = ftanh(g0.z), o_ = fsig(g0.w);
            c0 = f_ * c0 + i_ * gg;
            Hdst[jg0] = o_ * ftanh(c0);
            i_ = fsig(g1v.x); f_ = fsig(g1v.y);
            gg = ftanh(g1v.z); o_ = fsig(g1v.w);
            c1 = f_ * c1 + i_ * gg;
            Hdst[jg1] = o_ * ftanh(c1);
        }

        // per-bg-group barrier: release-arrive + acquire-spin
        if (s + 1 < TST) {
            __syncthreads();
            if (tid == 0) {
                asm volatile("red.release.gpu.global.add.u32 [%0], %1;"
                             :: "l"(ctr), "r"(1u) : "memory");
                unsigned tgt = 32u * (unsigned)(s + 1);
                unsigned v;
                do {
                    asm volatile("ld.acquire.gpu.global.u32 %0, [%1];"
                                 : "=r"(v) : "l"(ctr));
                } while (v < tgt);
            }
            __syncthreads();
        }
    }
}

// ---------------- Sinkhorn on K[t][b][n] ------------------------------------
__global__ void sink_row() {   // u[b][t] = 1 / sum_n K[t][b][n] v[b][n]
    int b = blockIdx.y;
    int m = blockIdx.x * 8 + (threadIdx.x >> 5);
    int lane = threadIdx.x & 31;
    const float* Kr = g_K + ((size_t)m * BATCH + b) * NN;
    const float* vv = g_v + b * NN;
    float acc = 0.f;
#pragma unroll
    for (int i = 0; i < 8; ++i) acc += Kr[lane + 32 * i] * vv[lane + 32 * i];
#pragma unroll
    for (int o = 16; o; o >>= 1) acc += __shfl_xor_sync(0xFFFFFFFFu, acc, o);
    if (!lane) g_u[b * NN + m] = 1.f / acc;
}

__global__ void sink_col() {   // v[b][n] = 1 / sum_t K[t][b][n] u[b][t]
    int b = blockIdx.y;
    int n = blockIdx.x * 64 + (threadIdx.x & 63);
    int part = threadIdx.x >> 6;
    const float* Kb = g_K + (size_t)b * NN;
    const float* uu = g_u + b * NN;
    float acc = 0.f;
    for (int m = part; m < NN; m += 4)
        acc += Kb[(size_t)m * BATCH * NN + n] * uu[m];
    __shared__ float s[256];
    s[threadIdx.x] = acc;
    __syncthreads();
    if (threadIdx.x < 64) {
        float r = s[threadIdx.x] + s[threadIdx.x + 64] + s[threadIdx.x + 128] +
                  s[threadIdx.x + 192];
        g_v[b * NN + n] = 1.f / r;
    }
}

__global__ void sink_out(float* __restrict__ out) {
    int b = blockIdx.y, m = blockIdx.x, n = threadIdx.x;
    out[((size_t)b * NN + m) * NN + n] =
        g_u[b * NN + m] * g_K[((size_t)m * BATCH + b) * NN + n] *
        g_v[b * NN + n];
}

// ---------------------------------------------------------------------------
extern "C" void kernel_launch(void* const* d_in, const int* in_sizes, int n_in,
                              void* d_out, int out_size)
{
    const float* x     = (const float*)d_in[0];
    const float* W_emb = (const float*)d_in[1];
    const float* b_emb = (const float*)d_in[2];
    const float* W_ih  = (const float*)d_in[3];
    const float* W_hh  = (const float*)d_in[4];
    const float* b_ih  = (const float*)d_in[5];
    const float* b_hh  = (const float*)d_in[6];
    const float* W_fc  = (const float*)d_in[7];
    const float* b_fc  = (const float*)d_in[8];
    float* out = (float*)d_out;

    float *gG, *gS, *gXP, *gHS, *gK, *gWr, *gWi, *gbr;
    cudaGetSymbolAddress((void**)&gG,  g_G);
    cudaGetSymbolAddress((void**)&gS,  g_S);
    cudaGetSymbolAddress((void**)&gXP, g_XP);
    cudaGetSymbolAddress((void**)&gHS, g_HS);
    cudaGetSymbolAddress((void**)&gK,  g_K);
    cudaGetSymbolAddress((void**)&gWr, g_Wr);
    cudaGetSymbolAddress((void**)&gWi, g_Wi);
    cudaGetSymbolAddress((void**)&gbr, g_br);

    static bool attr_set = false;
    if (!attr_set) {
        cudaFuncSetAttribute(lstm_persist,
                             cudaFuncAttributeMaxDynamicSharedMemorySize,
                             LSTM_SMEM);
        attr_set = true;
    }

    init_k<<<128, 256>>>();
    reorder_k<<<4096, 256>>>(W_ih, W_hh, b_ih, b_hh);
    embed_kernel<<<dim3(32, 128), 256>>>(x, W_emb, b_emb);

    // S[b] = g2[b] @ g1[b]^T  (M=N=256, K=256, batched over 128)
    gemm128<0><<<dim3(2, 2, 128), 256>>>(
        gG + (size_t)NN * EMB, EMB, (size_t)2 * NN * EMB, (size_t)128 * EMB,
        gG, EMB, (size_t)2 * NN * EMB,
        nullptr, gS, NN, (size_t)NN * NN, EMB);

    // XP[s][b][:] = S[b][s][:] @ Wi^T + br   (tile y = step s, ldA=NN*NN)
    gemm128<1><<<dim3(16, 256, 1), 256>>>(
        gS, NN * NN, 0, (size_t)NN,
        gWi, NN, 0, gbr, gXP, G4, 0, NN);

    // fused persistent LSTM: 256 steps in one launch (time-major HS)
    lstm_persist<<<128, 256, LSTM_SMEM>>>(gXP, gWr, gHS);

    // K[t][b][:] = exp(HS[t][b][:] @ W_fc^T + b_fc)
    gemm128<2><<<dim3(2, 256, 1), 256>>>(
        gHS, LD, 0, (size_t)128 * LD,
        W_fc, LD, 0, b_fc, gK, NN, 0, LD);

    // Sinkhorn: 5 x (u = 1/(Kv); v = 1/(K^T u)), then combine
    for (int it = 0; it < 5; ++it) {
        sink_row<<<dim3(32, 128), 256>>>();
        sink_col<<<dim3(4, 128), 256>>>();
    }
    sink_out<<<dim3(256, 128), 256>>>(out);
}

// round 13
// speedup vs baseline: 1.0017x; 1.0017x over previous
#include <cuda_runtime.h>
#include <math.h>

#define BATCH 128
#define NN 256
#define EMB 256
#define LD 512
#define TST 256
#define G4 2048

// ---------------- scratch (device globals; no allocations) ------------------
__device__ float g_G[(size_t)BATCH*2*NN*EMB];     // embedded g1|g2
__device__ float g_S[(size_t)BATCH*NN*NN];        // similarity [b][t][n]
__device__ float g_XP[(size_t)TST*BATCH*G4];      // [s][b][r] xt@W_ih^T + biases
__device__ float g_HS[(size_t)TST*BATCH*LD];      // [s][b][j] all h_t
__device__ float g_K[(size_t)TST*BATCH*NN];       // [t][b][n] exp(M)
__device__ float g_u[BATCH*NN];
__device__ float g_v[BATCH*NN];
__device__ float g_Wr[G4*LD];                     // W_hh reordered (rows 4j+gate)
__device__ float g_Wi[G4*NN];                     // W_ih reordered
__device__ float g_br[G4];                        // b_ih+b_hh reordered
__device__ unsigned g_barctr4[4*32];              // per-bg barrier counters

// ---------------- packed f32x2 helpers --------------------------------------
__device__ __forceinline__ unsigned long long pk2(float lo, float hi) {
    unsigned long long r;
    asm("mov.b64 %0, {%1, %2};" : "=l"(r) : "f"(lo), "f"(hi));
    return r;
}
__device__ __forceinline__ void upk2(unsigned long long v, float &lo, float &hi) {
    asm("mov.b64 {%0, %1}, %2;" : "=f"(lo), "=f"(hi) : "l"(v));
}
__device__ __forceinline__ void fma2(unsigned long long &d, unsigned long long a,
                                     unsigned long long b) {
    asm("fma.rn.f32x2 %0, %1, %2, %0;" : "+l"(d) : "l"(a), "l"(b));
}
__device__ __forceinline__ void add2(unsigned long long &d, unsigned long long a) {
    asm("add.rn.f32x2 %0, %0, %1;" : "+l"(d) : "l"(a));
}

__device__ __forceinline__ float fsig(float x) {
    return 1.f / (1.f + __expf(-x));
}
__device__ __forceinline__ float ftanh(float x) {
    return 1.f - 2.f / (1.f + __expf(2.f * x));
}

// ---------------- init: barrier ctrs; v = 1 ---------------------------------
__global__ void init_k() {
    int i = blockIdx.x * 256 + threadIdx.x;
    if (i < BATCH * NN) g_v[i] = 1.f;
    if (i < 128) g_barctr4[i] = 0u;
}

// ---------------- reorder W_hh/W_ih rows to 4j+gate; combine biases ---------
__global__ void reorder_k(const float* __restrict__ W_ih,
                          const float* __restrict__ W_hh,
                          const float* __restrict__ b_ih,
                          const float* __restrict__ b_hh) {
    int idx = blockIdx.x * 256 + threadIdx.x;    // G4*LD = 1048576
    int R = idx >> 9, k = idx & 511;
    int j = R >> 2, gt = R & 3;
    int src = gt * 512 + j;
    g_Wr[(size_t)R * LD + k] = W_hh[(size_t)src * LD + k];
    if (k < NN) g_Wi[(size_t)R * NN + k] = W_ih[(size_t)src * NN + k];
    if (k == 0) g_br[R] = b_ih[src] + b_hh[src];
}

// ---------------- embedding + leaky relu ------------------------------------
__global__ void __launch_bounds__(256) embed_kernel(
    const float* __restrict__ x, const float* __restrict__ W_emb,
    const float* __restrict__ b_emb)
{
    __shared__ float sW[32 * 256];
    __shared__ float sx[16 * 32];
    int tid = threadIdx.x;
    int b = blockIdx.y;
    int p0 = blockIdx.x * 16;
    for (int idx = tid; idx < 256 * 32; idx += 256) {
        int e = idx >> 5, f = idx & 31;
        sW[f * 256 + e] = W_emb[idx];
    }
    for (int idx = tid; idx < 512; idx += 256)
        sx[idx] = x[((size_t)b * 512 + p0) * 32 + idx];
    __syncthreads();
    int e = tid;
    float bias = b_emb[e];
    float acc[16];
#pragma unroll
    for (int r = 0; r < 16; ++r) acc[r] = bias;
#pragma unroll
    for (int f = 0; f < 32; ++f) {
        float w = sW[f * 256 + e];
#pragma unroll
        for (int r = 0; r < 16; ++r) acc[r] += sx[r * 32 + f] * w;
    }
#pragma unroll
    for (int r = 0; r < 16; ++r) {
        float v = acc[r];
        v = (v > 0.f) ? v : 0.01f * v;
        g_G[((size_t)b * 512 + p0 + r) * 256 + e] = v;
    }
}

// ---------------- gemm128 v3: duplicated-A smem (no pk2 in hot loop) --------
// C[m,n]=sum_k A[m,k]B[n,k]; 128x128 tile, 256 threads, 8x8 microtile, f32x2.
// A stored in smem as (a,a) pairs -> direct LDS.128 of packed operands.
// MODE 0: plain   MODE 1: +bias[n]   MODE 2: __expf(acc + bias[n])
template <int MODE>
__global__ void __launch_bounds__(256, 2) gemm128(
    const float* __restrict__ A, int ldA, size_t Abat, size_t Astep,
    const float* __restrict__ B, int ldB, size_t Bbat,
    const float* __restrict__ bias,
    float* __restrict__ C, int ldC, size_t Cbat, int K)
{
    __shared__ __align__(16) float Asd[2][16 * 256];   // duplicated pairs
    __shared__ __align__(16) float Bs[2][16 * 128];
    int tid = threadIdx.x;
    int tx = tid & 15, ty = tid >> 4;
    size_t zo = blockIdx.z;
    A += zo * Abat + (size_t)blockIdx.y * Astep;
    B += zo * Bbat + (size_t)blockIdx.x * 128 * ldB;
    C += zo * Cbat + (size_t)blockIdx.y * 128 * ldC + (size_t)blockIdx.x * 128;

    int lrow = tid >> 1, lkq = (tid & 1) * 8;
    const float* Ald = A + (size_t)lrow * ldA + lkq;
    const float* Bld = B + (size_t)lrow * ldB + lkq;

    unsigned long long acc[8][4];
#pragma unroll
    for (int i = 0; i < 8; ++i)
#pragma unroll
        for (int j = 0; j < 4; ++j) acc[i][j] = 0ULL;

#define ST_TILE(BUF, AV0, AV1, BV0, BV1) do {                                  \
    unsigned long long _pp;                                                    \
    _pp = pk2((AV0).x, (AV0).x);                                               \
    *(unsigned long long*)&Asd[BUF][(lkq + 0) * 256 + 2 * lrow] = _pp;         \
    _pp = pk2((AV0).y, (AV0).y);                                               \
    *(unsigned long long*)&Asd[BUF][(lkq + 1) * 256 + 2 * lrow] = _pp;         \
    _pp = pk2((AV0).z, (AV0).z);                                               \
    *(unsigned long long*)&Asd[BUF][(lkq + 2) * 256 + 2 * lrow] = _pp;         \
    _pp = pk2((AV0).w, (AV0).w);                                               \
    *(unsigned long long*)&Asd[BUF][(lkq + 3) * 256 + 2 * lrow] = _pp;         \
    _pp = pk2((AV1).x, (AV1).x);                                               \
    *(unsigned long long*)&Asd[BUF][(lkq + 4) * 256 + 2 * lrow] = _pp;         \
    _pp = pk2((AV1).y, (AV1).y);                                               \
    *(unsigned long long*)&Asd[BUF][(lkq + 5) * 256 + 2 * lrow] = _pp;         \
    _pp = pk2((AV1).z, (AV1).z);                                               \
    *(unsigned long long*)&Asd[BUF][(lkq + 6) * 256 + 2 * lrow] = _pp;         \
    _pp = pk2((AV1).w, (AV1).w);                                               \
    *(unsigned long long*)&Asd[BUF][(lkq + 7) * 256 + 2 * lrow] = _pp;         \
    Bs[BUF][(lkq + 0) * 128 + lrow] = (BV0).x;                                 \
    Bs[BUF][(lkq + 1) * 128 + lrow] = (BV0).y;                                 \
    Bs[BUF][(lkq + 2) * 128 + lrow] = (BV0).z;                                 \
    Bs[BUF][(lkq + 3) * 128 + lrow] = (BV0).w;                                 \
    Bs[BUF][(lkq + 4) * 128 + lrow] = (BV1).x;                                 \
    Bs[BUF][(lkq + 5) * 128 + lrow] = (BV1).y;                                 \
    Bs[BUF][(lkq + 6) * 128 + lrow] = (BV1).z;                                 \
    Bs[BUF][(lkq + 7) * 128 + lrow] = (BV1).w;                                 \
} while (0)

    float4 av0 = *(const float4*)(Ald);
    float4 av1 = *(const float4*)(Ald + 4);
    float4 bv0 = *(const float4*)(Bld);
    float4 bv1 = *(const float4*)(Bld + 4);
    ST_TILE(0, av0, av1, bv0, bv1);
    __syncthreads();

    int NT = K >> 4;
    int p = 0;
    for (int it = 0; it < NT; ++it) {
        if (it + 1 < NT) {
            int kt = (it + 1) << 4;
            av0 = *(const float4*)(Ald + kt);
            av1 = *(const float4*)(Ald + kt + 4);
            bv0 = *(const float4*)(Bld + kt);
            bv1 = *(const float4*)(Bld + kt + 4);
        }
        const float* Ap = Asd[p];
        const float* Bp = Bs[p];
#pragma unroll
        for (int kk = 0; kk < 16; ++kk) {
            ulonglong2 a01 = *(const ulonglong2*)&Ap[kk * 256 + ty * 8];
            ulonglong2 a23 = *(const ulonglong2*)&Ap[kk * 256 + ty * 8 + 4];
            ulonglong2 a45 = *(const ulonglong2*)&Ap[kk * 256 + 128 + ty * 8];
            ulonglong2 a67 = *(const ulonglong2*)&Ap[kk * 256 + 128 + ty * 8 + 4];
            ulonglong2 b0 = *(const ulonglong2*)&Bp[kk * 128 + tx * 4];
            ulonglong2 b1 = *(const ulonglong2*)&Bp[kk * 128 + 64 + tx * 4];
            fma2(acc[0][0], a01.x, b0.x); fma2(acc[0][1], a01.x, b0.y);
            fma2(acc[0][2], a01.x, b1.x); fma2(acc[0][3], a01.x, b1.y);
            fma2(acc[1][0], a01.y, b0.x); fma2(acc[1][1], a01.y, b0.y);
            fma2(acc[1][2], a01.y, b1.x); fma2(acc[1][3], a01.y, b1.y);
            fma2(acc[2][0], a23.x, b0.x); fma2(acc[2][1], a23.x, b0.y);
            fma2(acc[2][2], a23.x, b1.x); fma2(acc[2][3], a23.x, b1.y);
            fma2(acc[3][0], a23.y, b0.x); fma2(acc[3][1], a23.y, b0.y);
            fma2(acc[3][2], a23.y, b1.x); fma2(acc[3][3], a23.y, b1.y);
            fma2(acc[4][0], a45.x, b0.x); fma2(acc[4][1], a45.x, b0.y);
            fma2(acc[4][2], a45.x, b1.x); fma2(acc[4][3], a45.x, b1.y);
            fma2(acc[5][0], a45.y, b0.x); fma2(acc[5][1], a45.y, b0.y);
            fma2(acc[5][2], a45.y, b1.x); fma2(acc[5][3], a45.y, b1.y);
            fma2(acc[6][0], a67.x, b0.x); fma2(acc[6][1], a67.x, b0.y);
            fma2(acc[6][2], a67.x, b1.x); fma2(acc[6][3], a67.x, b1.y);
            fma2(acc[7][0], a67.y, b0.x); fma2(acc[7][1], a67.y, b0.y);
            fma2(acc[7][2], a67.y, b1.x); fma2(acc[7][3], a67.y, b1.y);
        }
        if (it + 1 < NT) {
            int q = p ^ 1;
            ST_TILE(q, av0, av1, bv0, bv1);
        }
        __syncthreads();
        p ^= 1;
    }
#undef ST_TILE

    int nb0 = blockIdx.x * 128 + tx * 4;
#pragma unroll
    for (int i = 0; i < 8; ++i) {
        int m = (i < 4) ? (ty * 4 + i) : (64 + ty * 4 + (i - 4));
#pragma unroll
        for (int half = 0; half < 2; ++half) {
            float r0, r1, r2, r3;
            upk2(acc[i][half * 2 + 0], r0, r1);
            upk2(acc[i][half * 2 + 1], r2, r3);
            int nb = nb0 + half * 64;
            if (MODE == 1) {
                r0 += bias[nb + 0]; r1 += bias[nb + 1];
                r2 += bias[nb + 2]; r3 += bias[nb + 3];
            }
            if (MODE == 2) {
                r0 = __expf(r0 + bias[nb + 0]); r1 = __expf(r1 + bias[nb + 1]);
                r2 = __expf(r2 + bias[nb + 2]); r3 = __expf(r3 + bias[nb + 3]);
            }
            float4 o; o.x = r0; o.y = r1; o.z = r2; o.w = r3;
            *(float4*)(C + (size_t)m * ldC + tx * 4 + half * 64) = o;
        }
    }
}

// ---------------- persistent fused LSTM v5 (k-chunk staged pipeline) --------
// 128 blocks x 256 threads. Block (rg=bid&31, bg=bid>>5): gate-rows
// [rg*64,+64) (hidden [rg*16,+16)), batches [bg*32,+32).
// k split into 4 chunks of 128; H chunk c+1 staged (LDG early, STS late) while
// chunk c is FMA'd from the other buffer. Warp w owns k {c*128+w*16..+15}.
// W smem-resident with per-8-row pad; partials [warp][b*68+r]; per-bg barrier.
#define HS_CH 132
#define PSTR 68
#define WSZ (64 * 516 + 32)
#define PART_OFF WSZ
#define PART_SZ (8 * 32 * PSTR)        /* 17408 >= 2 chunk buffers (8448) */
#define LSTM_SMEM ((WSZ + PART_SZ) * 4)

__device__ __forceinline__ int woff(int r) { return r * 516 + ((r >> 3) << 2); }

__global__ void __launch_bounds__(256, 1) lstm_persist(
    const float* __restrict__ XP, const float* __restrict__ Wr,
    float* __restrict__ HS)
{
    extern __shared__ float sm[];
    float* Ws = sm;
    float* Hbuf0 = sm + PART_OFF;          // 32 x 132
    float* Hbuf1 = Hbuf0 + 32 * HS_CH;     // 32 x 132
    float* part = sm + PART_OFF;           // aliases H buffers (used after GEMM)

    int tid = threadIdx.x;
    int rg = blockIdx.x & 31;
    int bg = blockIdx.x >> 5;
    int warp = tid >> 5;
    int lane = tid & 31;
    int bq = lane & 3;
    int rq = (lane >> 2) & 7;
    int wk16 = warp * 16;                  // warp's k offset within a chunk

    // load W slice once (64 rows x 512) with per-8-row pad
    for (int i = tid; i < 64 * 128; i += 256) {
        int r = i >> 7, kq = (i & 127) * 4;
        float4 v = *(const float4*)&Wr[(size_t)(rg * 64 + r) * LD + kq];
        *(float4*)&Ws[woff(r) + kq] = v;
    }

    int bl = tid & 31;
    int h0 = tid >> 5;                     // 0..7 ; pair handles h0 and h0+8
    int bgl = bg * 32 + bl;
    int jg0 = rg * 16 + h0, jg1 = jg0 + 8;
    float c0 = 0.f, c1 = 0.f;
    unsigned* ctr = &g_barctr4[bg * 32];
    int wbase = rq * 516;                  // row rq+8j at rq*516 + j*4132

    __syncthreads();

    for (int s = 0; s < TST; ++s) {
        // XP gate prefetch (time-major slab)
        const float* xpr = &XP[((size_t)s * BATCH + bgl) * G4 + rg * 64];
        float4 g0 = *(const float4*)&xpr[4 * h0];
        float4 g1v = *(const float4*)&xpr[4 * h0 + 32];

        if (s > 0) {
            const float* Hsrc = HS + ((size_t)(s - 1) * BATCH + bg * 32) * LD;

            // stage chunk 0
#pragma unroll
            for (int j = 0; j < 4; ++j) {
                int i = tid + j * 256;
                int b = i >> 5, kq = (i & 31) * 4;
                float4 v = *(const float4*)&Hsrc[(size_t)b * LD + kq];
                *(float4*)&Hbuf0[b * HS_CH + kq] = v;
            }
            __syncthreads();

            unsigned long long acc[8][8];
#pragma unroll
            for (int i = 0; i < 8; ++i)
#pragma unroll
                for (int j = 0; j < 8; ++j) acc[i][j] = 0ULL;

#pragma unroll 1
            for (int c = 0; c < 4; ++c) {
                // issue next chunk's global loads first (latency overlap)
                float4 st[4];
                if (c < 3) {
#pragma unroll
                    for (int j = 0; j < 4; ++j) {
                        int i = tid + j * 256;
                        int b = i >> 5, kq = (i & 31) * 4;
                        st[j] = *(const float4*)
                            &Hsrc[(size_t)b * LD + (c + 1) * 128 + kq];
                    }
                }
                const float* Hc = (c & 1) ? Hbuf1 : Hbuf0;
                int kc = c * 128 + wk16;
#pragma unroll
                for (int q = 0; q < 4; ++q) {
                    int k4 = q * 4;
                    ulonglong2 h4[8], w4[8];
#pragma unroll
                    for (int i = 0; i < 8; ++i)
                        h4[i] = *(const ulonglong2*)
                            &Hc[(bq + 4 * i) * HS_CH + wk16 + k4];
#pragma unroll
                    for (int j = 0; j < 8; ++j)
                        w4[j] = *(const ulonglong2*)
                            &Ws[wbase + j * 4132 + kc + k4];
#pragma unroll
                    for (int i = 0; i < 8; ++i)
#pragma unroll
                        for (int j = 0; j < 8; ++j) {
                            fma2(acc[i][j], h4[i].x, w4[j].x);
                            fma2(acc[i][j], h4[i].y, w4[j].y);
                        }
                }
                if (c < 3) {
                    float* Hn = ((c + 1) & 1) ? Hbuf1 : Hbuf0;
#pragma unroll
                    for (int j = 0; j < 4; ++j) {
                        int i = tid + j * 256;
                        int b = i >> 5, kq = (i & 31) * 4;
                        *(float4*)&Hn[b * HS_CH + kq] = st[j];
                    }
                }
                __syncthreads();
            }

            // partials: part[warp][b*68 + r], r = rq+8j
            float* pw = part + warp * (32 * PSTR);
#pragma unroll
            for (int i = 0; i < 8; ++i) {
                float* pb = pw + (bq + 4 * i) * PSTR + rq;
#pragma unroll
                for (int j = 0; j < 8; ++j) {
                    float lo, hi; upk2(acc[i][j], lo, hi);
                    pb[8 * j] = lo + hi;
                }
            }
            __syncthreads();

            // reduce 8 warps: LDS.128 + packed adds
            ulonglong2 A0 = *(ulonglong2*)&g0;
            ulonglong2 A1 = *(ulonglong2*)&g1v;
#pragma unroll
            for (int w = 0; w < 8; ++w) {
                const float* pr = part + w * (32 * PSTR) + bl * PSTR;
                ulonglong2 qa = *(const ulonglong2*)&pr[4 * h0];
                ulonglong2 qb = *(const ulonglong2*)&pr[4 * h0 + 32];
                add2(A0.x, qa.x); add2(A0.y, qa.y);
                add2(A1.x, qb.x); add2(A1.y, qb.y);
            }
            *(ulonglong2*)&g0 = A0;
            *(ulonglong2*)&g1v = A1;
        }

        // gate order per hidden unit: [i, f, g, o]
        float* Hdst = &HS[((size_t)s * BATCH + bgl) * LD];
        {
            float i_ = fsig(g0.x), f_ = fsig(g0.y);
            float gg = ftanh(g0.z), o_ = fsig(g0.w);
            c0 = f_ * c0 + i_ * gg;
            Hdst[jg0] = o_ * ftanh(c0);
            i_ = fsig(g1v.x); f_ = fsig(g1v.y);
            gg = ftanh(g1v.z); o_ = fsig(g1v.w);
            c1 = f_ * c1 + i_ * gg;
            Hdst[jg1] = o_ * ftanh(c1);
        }

        // per-bg-group barrier: release-arrive + acquire-spin
        if (s + 1 < TST) {
            __syncthreads();
            if (tid == 0) {
                asm volatile("red.release.gpu.global.add.u32 [%0], %1;"
                             :: "l"(ctr), "r"(1u) : "memory");
                unsigned tgt = 32u * (unsigned)(s + 1);
                unsigned v;
                do {
                    asm volatile("ld.acquire.gpu.global.u32 %0, [%1];"
                                 : "=r"(v) : "l"(ctr));
                } while (v < tgt);
            }
            __syncthreads();
        }
    }
}

// ---------------- Sinkhorn on K[t][b][n] ------------------------------------
__global__ void sink_row() {   // u[b][t] = 1 / sum_n K[t][b][n] v[b][n]
    int b = blockIdx.y;
    int m = blockIdx.x * 8 + (threadIdx.x >> 5);
    int lane = threadIdx.x & 31;
    const float* Kr = g_K + ((size_t)m * BATCH + b) * NN;
    const float* vv = g_v + b * NN;
    float acc = 0.f;
#pragma unroll
    for (int i = 0; i < 8; ++i) acc += Kr[lane + 32 * i] * vv[lane + 32 * i];
#pragma unroll
    for (int o = 16; o; o >>= 1) acc += __shfl_xor_sync(0xFFFFFFFFu, acc, o);
    if (!lane) g_u[b * NN + m] = 1.f / acc;
}

__global__ void sink_col() {   // v[b][n] = 1 / sum_t K[t][b][n] u[b][t]
    int b = blockIdx.y;
    int n = blockIdx.x * 64 + (threadIdx.x & 63);
    int part = threadIdx.x >> 6;
    const float* Kb = g_K + (size_t)b * NN;
    const float* uu = g_u + b * NN;
    float acc = 0.f;
    for (int m = part; m < NN; m += 4)
        acc += Kb[(size_t)m * BATCH * NN + n] * uu[m];
    __shared__ float s[256];
    s[threadIdx.x] = acc;
    __syncthreads();
    if (threadIdx.x < 64) {
        float r = s[threadIdx.x] + s[threadIdx.x + 64] + s[threadIdx.x + 128] +
                  s[threadIdx.x + 192];
        g_v[b * NN + n] = 1.f / r;
    }
}

__global__ void sink_out(float* __restrict__ out) {
    int b = blockIdx.y, m = blockIdx.x, n = threadIdx.x;
    out[((size_t)b * NN + m) * NN + n] =
        g_u[b * NN + m] * g_K[((size_t)m * BATCH + b) * NN + n] *
        g_v[b * NN + n];
}

// ---------------------------------------------------------------------------
extern "C" void kernel_launch(void* const* d_in, const int* in_sizes, int n_in,
                              void* d_out, int out_size)
{
    const float* x     = (const float*)d_in[0];
    const float* W_emb = (const float*)d_in[1];
    const float* b_emb = (const float*)d_in[2];
    const float* W_ih  = (const float*)d_in[3];
    const float* W_hh  = (const float*)d_in[4];
    const float* b_ih  = (const float*)d_in[5];
    const float* b_hh  = (const float*)d_in[6];
    const float* W_fc  = (const float*)d_in[7];
    const float* b_fc  = (const float*)d_in[8];
    float* out = (float*)d_out;

    float *gG, *gS, *gXP, *gHS, *gK, *gWr, *gWi, *gbr;
    cudaGetSymbolAddress((void**)&gG,  g_G);
    cudaGetSymbolAddress((void**)&gS,  g_S);
    cudaGetSymbolAddress((void**)&gXP, g_XP);
    cudaGetSymbolAddress((void**)&gHS, g_HS);
    cudaGetSymbolAddress((void**)&gK,  g_K);
    cudaGetSymbolAddress((void**)&gWr, g_Wr);
    cudaGetSymbolAddress((void**)&gWi, g_Wi);
    cudaGetSymbolAddress((void**)&gbr, g_br);

    static bool attr_set = false;
    if (!attr_set) {
        cudaFuncSetAttribute(lstm_persist,
                             cudaFuncAttributeMaxDynamicSharedMemorySize,
                             LSTM_SMEM);
        attr_set = true;
    }

    init_k<<<128, 256>>>();
    reorder_k<<<4096, 256>>>(W_ih, W_hh, b_ih, b_hh);
    embed_kernel<<<dim3(32, 128), 256>>>(x, W_emb, b_emb);

    // S[b] = g2[b] @ g1[b]^T  (M=N=256, K=256, batched over 128)
    gemm128<0><<<dim3(2, 2, 128), 256>>>(
        gG + (size_t)NN * EMB, EMB, (size_t)2 * NN * EMB, (size_t)128 * EMB,
        gG, EMB, (size_t)2 * NN * EMB,
        nullptr, gS, NN, (size_t)NN * NN, EMB);

    // XP[s][b][:] = S[b][s][:] @ Wi^T + br   (tile y = step s, ldA=NN*NN)
    gemm128<1><<<dim3(16, 256, 1), 256>>>(
        gS, NN * NN, 0, (size_t)NN,
        gWi, NN, 0, gbr, gXP, G4, 0, NN);

    // fused persistent LSTM: 256 steps in one launch (time-major HS)
    lstm_persist<<<128, 256, LSTM_SMEM>>>(gXP, gWr, gHS);

    // K[t][b][:] = exp(HS[t][b][:] @ W_fc^T + b_fc)
    gemm128<2><<<dim3(2, 256, 1), 256>>>(
        gHS, LD, 0, (size_t)128 * LD,
        W_fc, LD, 0, b_fc, gK, NN, 0, LD);

    // Sinkhorn: 5 x (u = 1/(Kv); v = 1/(K^T u)), then combine
    for (int it = 0; it < 5; ++it) {
        sink_row<<<dim3(32, 128), 256>>>();
        sink_col<<<dim3(4, 128), 256>>>();
    }
    sink_out<<<dim3(256, 128), 256>>>(out);
}

// round 14
// speedup vs baseline: 1.0346x; 1.0329x over previous
#include <cuda_runtime.h>
#include <math.h>

#define BATCH 128
#define NN 256
#define EMB 256
#define LD 512
#define TST 256
#define G4 2048

// ---------------- scratch (device globals; no allocations) ------------------
__device__ float g_G[(size_t)BATCH*2*NN*EMB];     // embedded g1|g2
__device__ float g_S[(size_t)BATCH*NN*NN];        // similarity [b][t][n]
__device__ float g_XP[(size_t)TST*BATCH*G4];      // [s][b][r] xt@W_ih^T + biases
__device__ float g_HS[(size_t)TST*BATCH*LD];      // [s][b][j] all h_t
__device__ float g_K[(size_t)TST*BATCH*NN];       // [t][b][n] exp(M)
__device__ float g_u[BATCH*NN];
__device__ float g_v[BATCH*NN];
__device__ float g_Wr[G4*LD];                     // W_hh reordered (rows 4j+gate)
__device__ float g_Wi[G4*NN];                     // W_ih reordered
__device__ float g_br[G4];                        // b_ih+b_hh reordered
__device__ unsigned g_barctr4[4*32];              // per-bg barrier counters

// ---------------- packed f32x2 helpers --------------------------------------
__device__ __forceinline__ unsigned long long pk2(float lo, float hi) {
    unsigned long long r;
    asm("mov.b64 %0, {%1, %2};" : "=l"(r) : "f"(lo), "f"(hi));
    return r;
}
__device__ __forceinline__ void upk2(unsigned long long v, float &lo, float &hi) {
    asm("mov.b64 {%0, %1}, %2;" : "=f"(lo), "=f"(hi) : "l"(v));
}
__device__ __forceinline__ void fma2(unsigned long long &d, unsigned long long a,
                                     unsigned long long b) {
    asm("fma.rn.f32x2 %0, %1, %2, %0;" : "+l"(d) : "l"(a), "l"(b));
}
__device__ __forceinline__ void add2(unsigned long long &d, unsigned long long a) {
    asm("add.rn.f32x2 %0, %0, %1;" : "+l"(d) : "l"(a));
}

__device__ __forceinline__ float fsig(float x) {
    return 1.f / (1.f + __expf(-x));
}
__device__ __forceinline__ float ftanh(float x) {
    return 1.f - 2.f / (1.f + __expf(2.f * x));
}

// ---------------- init: barrier ctrs; v = 1 ---------------------------------
__global__ void init_k() {
    int i = blockIdx.x * 256 + threadIdx.x;
    if (i < BATCH * NN) g_v[i] = 1.f;
    if (i < 128) g_barctr4[i] = 0u;
}

// ---------------- reorder W_hh/W_ih rows to 4j+gate; combine biases ---------
__global__ void reorder_k(const float* __restrict__ W_ih,
                          const float* __restrict__ W_hh,
                          const float* __restrict__ b_ih,
                          const float* __restrict__ b_hh) {
    int idx = blockIdx.x * 256 + threadIdx.x;    // G4*LD = 1048576
    int R = idx >> 9, k = idx & 511;
    int j = R >> 2, gt = R & 3;
    int src = gt * 512 + j;
    g_Wr[(size_t)R * LD + k] = W_hh[(size_t)src * LD + k];
    if (k < NN) g_Wi[(size_t)R * NN + k] = W_ih[(size_t)src * NN + k];
    if (k == 0) g_br[R] = b_ih[src] + b_hh[src];
}

// ---------------- embedding + leaky relu ------------------------------------
__global__ void __launch_bounds__(256) embed_kernel(
    const float* __restrict__ x, const float* __restrict__ W_emb,
    const float* __restrict__ b_emb)
{
    __shared__ float sW[32 * 256];
    __shared__ float sx[16 * 32];
    int tid = threadIdx.x;
    int b = blockIdx.y;
    int p0 = blockIdx.x * 16;
    for (int idx = tid; idx < 256 * 32; idx += 256) {
        int e = idx >> 5, f = idx & 31;
        sW[f * 256 + e] = W_emb[idx];
    }
    for (int idx = tid; idx < 512; idx += 256)
        sx[idx] = x[((size_t)b * 512 + p0) * 32 + idx];
    __syncthreads();
    int e = tid;
    float bias = b_emb[e];
    float acc[16];
#pragma unroll
    for (int r = 0; r < 16; ++r) acc[r] = bias;
#pragma unroll
    for (int f = 0; f < 32; ++f) {
        float w = sW[f * 256 + e];
#pragma unroll
        for (int r = 0; r < 16; ++r) acc[r] += sx[r * 32 + f] * w;
    }
#pragma unroll
    for (int r = 0; r < 16; ++r) {
        float v = acc[r];
        v = (v > 0.f) ? v : 0.01f * v;
        g_G[((size_t)b * 512 + p0 + r) * 256 + e] = v;
    }
}

// ---------------- gemm128 v2: double-buffered smem, 1 sync/tile -------------
// C[m,n]=sum_k A[m,k]B[n,k]; 128x128 tile, 256 threads, 8x8 microtile, f32x2.
// MODE 0: plain   MODE 1: +bias[n]   MODE 2: __expf(acc + bias[n])
template <int MODE>
__global__ void __launch_bounds__(256, 2) gemm128(
    const float* __restrict__ A, int ldA, size_t Abat, size_t Astep,
    const float* __restrict__ B, int ldB, size_t Bbat,
    const float* __restrict__ bias,
    float* __restrict__ C, int ldC, size_t Cbat, int K)
{
    __shared__ __align__(16) float As[2][16 * 128];
    __shared__ __align__(16) float Bs[2][16 * 128];
    int tid = threadIdx.x;
    int tx = tid & 15, ty = tid >> 4;
    size_t zo = blockIdx.z;
    A += zo * Abat + (size_t)blockIdx.y * Astep;
    B += zo * Bbat + (size_t)blockIdx.x * 128 * ldB;
    C += zo * Cbat + (size_t)blockIdx.y * 128 * ldC + (size_t)blockIdx.x * 128;

    int lrow = tid >> 1, lkq = (tid & 1) * 8;
    const float* Ald = A + (size_t)lrow * ldA + lkq;
    const float* Bld = B + (size_t)lrow * ldB + lkq;

    unsigned long long acc[8][4];
#pragma unroll
    for (int i = 0; i < 8; ++i)
#pragma unroll
        for (int j = 0; j < 4; ++j) acc[i][j] = 0ULL;

    float4 av0 = *(const float4*)(Ald);
    float4 av1 = *(const float4*)(Ald + 4);
    float4 bv0 = *(const float4*)(Bld);
    float4 bv1 = *(const float4*)(Bld + 4);
    As[0][(lkq + 0) * 128 + lrow] = av0.x; As[0][(lkq + 1) * 128 + lrow] = av0.y;
    As[0][(lkq + 2) * 128 + lrow] = av0.z; As[0][(lkq + 3) * 128 + lrow] = av0.w;
    As[0][(lkq + 4) * 128 + lrow] = av1.x; As[0][(lkq + 5) * 128 + lrow] = av1.y;
    As[0][(lkq + 6) * 128 + lrow] = av1.z; As[0][(lkq + 7) * 128 + lrow] = av1.w;
    Bs[0][(lkq + 0) * 128 + lrow] = bv0.x; Bs[0][(lkq + 1) * 128 + lrow] = bv0.y;
    Bs[0][(lkq + 2) * 128 + lrow] = bv0.z; Bs[0][(lkq + 3) * 128 + lrow] = bv0.w;
    Bs[0][(lkq + 4) * 128 + lrow] = bv1.x; Bs[0][(lkq + 5) * 128 + lrow] = bv1.y;
    Bs[0][(lkq + 6) * 128 + lrow] = bv1.z; Bs[0][(lkq + 7) * 128 + lrow] = bv1.w;
    __syncthreads();

    int NT = K >> 4;
    int p = 0;
    for (int it = 0; it < NT; ++it) {
        if (it + 1 < NT) {
            int kt = (it + 1) << 4;
            av0 = *(const float4*)(Ald + kt);
            av1 = *(const float4*)(Ald + kt + 4);
            bv0 = *(const float4*)(Bld + kt);
            bv1 = *(const float4*)(Bld + kt + 4);
        }
        const float* Ap = As[p];
        const float* Bp = Bs[p];
#pragma unroll
        for (int kk = 0; kk < 16; ++kk) {
            float4 a0 = *(const float4*)&Ap[kk * 128 + ty * 4];
            float4 a1 = *(const float4*)&Ap[kk * 128 + 64 + ty * 4];
            ulonglong2 b0 = *(const ulonglong2*)&Bp[kk * 128 + tx * 4];
            ulonglong2 b1 = *(const ulonglong2*)&Bp[kk * 128 + 64 + tx * 4];
            unsigned long long ap;
            ap = pk2(a0.x, a0.x);
            fma2(acc[0][0], ap, b0.x); fma2(acc[0][1], ap, b0.y);
            fma2(acc[0][2], ap, b1.x); fma2(acc[0][3], ap, b1.y);
            ap = pk2(a0.y, a0.y);
            fma2(acc[1][0], ap, b0.x); fma2(acc[1][1], ap, b0.y);
            fma2(acc[1][2], ap, b1.x); fma2(acc[1][3], ap, b1.y);
            ap = pk2(a0.z, a0.z);
            fma2(acc[2][0], ap, b0.x); fma2(acc[2][1], ap, b0.y);
            fma2(acc[2][2], ap, b1.x); fma2(acc[2][3], ap, b1.y);
            ap = pk2(a0.w, a0.w);
            fma2(acc[3][0], ap, b0.x); fma2(acc[3][1], ap, b0.y);
            fma2(acc[3][2], ap, b1.x); fma2(acc[3][3], ap, b1.y);
            ap = pk2(a1.x, a1.x);
            fma2(acc[4][0], ap, b0.x); fma2(acc[4][1], ap, b0.y);
            fma2(acc[4][2], ap, b1.x); fma2(acc[4][3], ap, b1.y);
            ap = pk2(a1.y, a1.y);
            fma2(acc[5][0], ap, b0.x); fma2(acc[5][1], ap, b0.y);
            fma2(acc[5][2], ap, b1.x); fma2(acc[5][3], ap, b1.y);
            ap = pk2(a1.z, a1.z);
            fma2(acc[6][0], ap, b0.x); fma2(acc[6][1], ap, b0.y);
            fma2(acc[6][2], ap, b1.x); fma2(acc[6][3], ap, b1.y);
            ap = pk2(a1.w, a1.w);
            fma2(acc[7][0], ap, b0.x); fma2(acc[7][1], ap, b0.y);
            fma2(acc[7][2], ap, b1.x); fma2(acc[7][3], ap, b1.y);
        }
        if (it + 1 < NT) {
            int q = p ^ 1;
            As[q][(lkq + 0) * 128 + lrow] = av0.x; As[q][(lkq + 1) * 128 + lrow] = av0.y;
            As[q][(lkq + 2) * 128 + lrow] = av0.z; As[q][(lkq + 3) * 128 + lrow] = av0.w;
            As[q][(lkq + 4) * 128 + lrow] = av1.x; As[q][(lkq + 5) * 128 + lrow] = av1.y;
            As[q][(lkq + 6) * 128 + lrow] = av1.z; As[q][(lkq + 7) * 128 + lrow] = av1.w;
            Bs[q][(lkq + 0) * 128 + lrow] = bv0.x; Bs[q][(lkq + 1) * 128 + lrow] = bv0.y;
            Bs[q][(lkq + 2) * 128 + lrow] = bv0.z; Bs[q][(lkq + 3) * 128 + lrow] = bv0.w;
            Bs[q][(lkq + 4) * 128 + lrow] = bv1.x; Bs[q][(lkq + 5) * 128 + lrow] = bv1.y;
            Bs[q][(lkq + 6) * 128 + lrow] = bv1.z; Bs[q][(lkq + 7) * 128 + lrow] = bv1.w;
        }
        __syncthreads();
        p ^= 1;
    }

    int nb0 = blockIdx.x * 128 + tx * 4;
#pragma unroll
    for (int i = 0; i < 8; ++i) {
        int m = (i < 4) ? (ty * 4 + i) : (64 + ty * 4 + (i - 4));
#pragma unroll
        for (int half = 0; half < 2; ++half) {
            float r0, r1, r2, r3;
            upk2(acc[i][half * 2 + 0], r0, r1);
            upk2(acc[i][half * 2 + 1], r2, r3);
            int nb = nb0 + half * 64;
            if (MODE == 1) {
                r0 += bias[nb + 0]; r1 += bias[nb + 1];
                r2 += bias[nb + 2]; r3 += bias[nb + 3];
            }
            if (MODE == 2) {
                r0 = __expf(r0 + bias[nb + 0]); r1 = __expf(r1 + bias[nb + 1]);
                r2 = __expf(r2 + bias[nb + 2]); r3 = __expf(r3 + bias[nb + 3]);
            }
            float4 o; o.x = r0; o.y = r1; o.z = r2; o.w = r3;
            *(float4*)(C + (size_t)m * ldC + tx * 4 + half * 64) = o;
        }
    }
}

// ---------------- persistent fused LSTM v4b ---------------------------------
// 128 blocks x 256 threads. Block (rg=bid&31, bg=bid>>5): gate-rows
// [rg*64,+64) (hidden [rg*16,+16)), batches [bg*32,+32).
// W slice smem-resident with per-8-row pad (conflict-free fragment loads).
// Partials laid out [warp][b*68+r] -> reduce via LDS.128 + add.f32x2.
// Barrier: pre-arrive syncthreads, tid0 red.release, then ALL threads
// acquire-spin (no trailing bar.sync; no wake broadcast).
#define HS_STRIDE 516
#define PSTR 68
#define WSZ (64 * 516 + 32)            /* 64 rows + 8 pads of 4 */
#define PART_OFF WSZ
#define PART_SZ (8 * 32 * PSTR)        /* 17408 >= Hs 32*516 */
#define LSTM_SMEM ((WSZ + PART_SZ) * 4)

__device__ __forceinline__ int woff(int r) { return r * 516 + ((r >> 3) << 2); }

__global__ void __launch_bounds__(256, 1) lstm_persist(
    const float* __restrict__ XP, const float* __restrict__ Wr,
    float* __restrict__ HS)
{
    extern __shared__ float sm[];
    float* Ws = sm;
    float* Hs = sm + PART_OFF;        // staging aliases partial region
    float* part = Hs;

    int tid = threadIdx.x;
    int rg = blockIdx.x & 31;
    int bg = blockIdx.x >> 5;
    int warp = tid >> 5;
    int lane = tid & 31;
    int bq = lane & 3;
    int rq = (lane >> 2) & 7;
    int kbase = warp * 64;

    // load W slice once (64 rows x 512) with per-8-row pad
    for (int i = tid; i < 64 * 128; i += 256) {
        int r = i >> 7, kq = (i & 127) * 4;
        float4 v = *(const float4*)&Wr[(size_t)(rg * 64 + r) * LD + kq];
        *(float4*)&Ws[woff(r) + kq] = v;
    }

    int bl = tid & 31;
    int h0 = tid >> 5;                 // 0..7 ; pair handles h0 and h0+8
    int bgl = bg * 32 + bl;
    int jg0 = rg * 16 + h0, jg1 = jg0 + 8;
    float c0 = 0.f, c1 = 0.f;
    unsigned* ctr = &g_barctr4[bg * 32];
    // W fragment base: row rq+8j lives at rq*516 + j*4132
    int wbase = rq * 516 + kbase;

    __syncthreads();

    for (int s = 0; s < TST; ++s) {
        // XP gate prefetch (time-major slab)
        const float* xpr = &XP[((size_t)s * BATCH + bgl) * G4 + rg * 64];
        float4 g0 = *(const float4*)&xpr[4 * h0];
        float4 g1v = *(const float4*)&xpr[4 * h0 + 32];

        if (s > 0) {
            // stage H from HS[s-1]: contiguous 64KB slab for this bg
            const float* Hsrc = HS + ((size_t)(s - 1) * BATCH + bg * 32) * LD;
            for (int i = tid; i < 32 * 128; i += 256) {
                int b = i >> 7, kq = (i & 127) * 4;
                float4 v = *(const float4*)&Hsrc[(size_t)b * LD + kq];
                *(float4*)&Hs[b * HS_STRIDE + kq] = v;
            }
            __syncthreads();

            unsigned long long acc[8][8];
#pragma unroll
            for (int i = 0; i < 8; ++i)
#pragma unroll
                for (int j = 0; j < 8; ++j) acc[i][j] = 0ULL;

#pragma unroll 1
            for (int q = 0; q < 16; ++q) {
                int k4 = q * 4;
                ulonglong2 h4[8], w4[8];
#pragma unroll
                for (int i = 0; i < 8; ++i)
                    h4[i] = *(const ulonglong2*)
                        &Hs[(bq + 4 * i) * HS_STRIDE + kbase + k4];
#pragma unroll
                for (int j = 0; j < 8; ++j)
                    w4[j] = *(const ulonglong2*)&Ws[wbase + j * 4132 + k4];
#pragma unroll
                for (int i = 0; i < 8; ++i)
#pragma unroll
                    for (int j = 0; j < 8; ++j) {
                        fma2(acc[i][j], h4[i].x, w4[j].x);
                        fma2(acc[i][j], h4[i].y, w4[j].y);
                    }
            }
            __syncthreads();   // Hs reads done before partial overwrite

            // partials: part[warp][b*68 + r], r = rq+8j
            float* pw = part + warp * (32 * PSTR);
#pragma unroll
            for (int i = 0; i < 8; ++i) {
                float* pb = pw + (bq + 4 * i) * PSTR + rq;
#pragma unroll
                for (int j = 0; j < 8; ++j) {
                    float lo, hi; upk2(acc[i][j], lo, hi);
                    pb[8 * j] = lo + hi;
                }
            }
            __syncthreads();

            // reduce 8 warps: LDS.128 + packed adds
            ulonglong2 A0 = *(ulonglong2*)&g0;
            ulonglong2 A1 = *(ulonglong2*)&g1v;
#pragma unroll
            for (int w = 0; w < 8; ++w) {
                const float* pr = part + w * (32 * PSTR) + bl * PSTR;
                ulonglong2 qa = *(const ulonglong2*)&pr[4 * h0];
                ulonglong2 qb = *(const ulonglong2*)&pr[4 * h0 + 32];
                add2(A0.x, qa.x); add2(A0.y, qa.y);
                add2(A1.x, qb.x); add2(A1.y, qb.y);
            }
            *(ulonglong2*)&g0 = A0;
            *(ulonglong2*)&g1v = A1;
        }

        // gate order per hidden unit: [i, f, g, o]
        float* Hdst = &HS[((size_t)s * BATCH + bgl) * LD];
        {
            float i_ = fsig(g0.x), f_ = fsig(g0.y);
            float gg = ftanh(g0.z), o_ = fsig(g0.w);
            c0 = f_ * c0 + i_ * gg;
            Hdst[jg0] = o_ * ftanh(c0);
            i_ = fsig(g1v.x); f_ = fsig(g1v.y);
            gg = ftanh(g1v.z); o_ = fsig(g1v.w);
            c1 = f_ * c1 + i_ * gg;
            Hdst[jg1] = o_ * ftanh(c1);
        }

        // per-bg-group barrier: tid0 release-arrive, ALL threads acquire-spin.
        // Pre-arrive sync orders all warps' smem reads & H stores before the
        // arrive; each thread proceeds as soon as it observes the release.
        if (s + 1 < TST) {
            __syncthreads();
            if (tid == 0) {
                asm volatile("red.release.gpu.global.add.u32 [%0], %1;"
                             :: "l"(ctr), "r"(1u) : "memory");
            }
            unsigned tgt = 32u * (unsigned)(s + 1);
            unsigned v;
            do {
                asm volatile("ld.acquire.gpu.global.u32 %0, [%1];"
                             : "=r"(v) : "l"(ctr));
            } while (v < tgt);
        }
    }
}

// ---------------- Sinkhorn on K[t][b][n] ------------------------------------
__global__ void sink_row() {   // u[b][t] = 1 / sum_n K[t][b][n] v[b][n]
    int b = blockIdx.y;
    int m = blockIdx.x * 8 + (threadIdx.x >> 5);
    int lane = threadIdx.x & 31;
    const float* Kr = g_K + ((size_t)m * BATCH + b) * NN;
    const float* vv = g_v + b * NN;
    float acc = 0.f;
#pragma unroll
    for (int i = 0; i < 8; ++i) acc += Kr[lane + 32 * i] * vv[lane + 32 * i];
#pragma unroll
    for (int o = 16; o; o >>= 1) acc += __shfl_xor_sync(0xFFFFFFFFu, acc, o);
    if (!lane) g_u[b * NN + m] = 1.f / acc;
}

__global__ void sink_col() {   // v[b][n] = 1 / sum_t K[t][b][n] u[b][t]
    int b = blockIdx.y;
    int n = blockIdx.x * 64 + (threadIdx.x & 63);
    int part = threadIdx.x >> 6;
    const float* Kb = g_K + (size_t)b * NN;
    const float* uu = g_u + b * NN;
    float acc = 0.f;
    for (int m = part; m < NN; m += 4)
        acc += Kb[(size_t)m * BATCH * NN + n] * uu[m];
    __shared__ float s[256];
    s[threadIdx.x] = acc;
    __syncthreads();
    if (threadIdx.x < 64) {
        float r = s[threadIdx.x] + s[threadIdx.x + 64] + s[threadIdx.x + 128] +
                  s[threadIdx.x + 192];
        g_v[b * NN + n] = 1.f / r;
    }
}

__global__ void sink_out(float* __restrict__ out) {
    int b = blockIdx.y, m = blockIdx.x, n = threadIdx.x;
    out[((size_t)b * NN + m) * NN + n] =
        g_u[b * NN + m] * g_K[((size_t)m * BATCH + b) * NN + n] *
        g_v[b * NN + n];
}

// ---------------------------------------------------------------------------
extern "C" void kernel_launch(void* const* d_in, const int* in_sizes, int n_in,
                              void* d_out, int out_size)
{
    const float* x     = (const float*)d_in[0];
    const float* W_emb = (const float*)d_in[1];
    const float* b_emb = (const float*)d_in[2];
    const float* W_ih  = (const float*)d_in[3];
    const float* W_hh  = (const float*)d_in[4];
    const float* b_ih  = (const float*)d_in[5];
    const float* b_hh  = (const float*)d_in[6];
    const float* W_fc  = (const float*)d_in[7];
    const float* b_fc  = (const float*)d_in[8];
    float* out = (float*)d_out;

    float *gG, *gS, *gXP, *gHS, *gK, *gWr, *gWi, *gbr;
    cudaGetSymbolAddress((void**)&gG,  g_G);
    cudaGetSymbolAddress((void**)&gS,  g_S);
    cudaGetSymbolAddress((void**)&gXP, g_XP);
    cudaGetSymbolAddress((void**)&gHS, g_HS);
    cudaGetSymbolAddress((void**)&gK,  g_K);
    cudaGetSymbolAddress((void**)&gWr, g_Wr);
    cudaGetSymbolAddress((void**)&gWi, g_Wi);
    cudaGetSymbolAddress((void**)&gbr, g_br);

    static bool attr_set = false;
    if (!attr_set) {
        cudaFuncSetAttribute(lstm_persist,
                             cudaFuncAttributeMaxDynamicSharedMemorySize,
                             LSTM_SMEM);
        attr_set = true;
    }

    init_k<<<128, 256>>>();
    reorder_k<<<4096, 256>>>(W_ih, W_hh, b_ih, b_hh);
    embed_kernel<<<dim3(32, 128), 256>>>(x, W_emb, b_emb);

    // S[b] = g2[b] @ g1[b]^T  (M=N=256, K=256, batched over 128)
    gemm128<0><<<dim3(2, 2, 128), 256>>>(
        gG + (size_t)NN * EMB, EMB, (size_t)2 * NN * EMB, (size_t)128 * EMB,
        gG, EMB, (size_t)2 * NN * EMB,
        nullptr, gS, NN, (size_t)NN * NN, EMB);

    // XP[s][b][:] = S[b][s][:] @ Wi^T + br   (tile y = step s, ldA=NN*NN)
    gemm128<1><<<dim3(16, 256, 1), 256>>>(
        gS, NN * NN, 0, (size_t)NN,
        gWi, NN, 0, gbr, gXP, G4, 0, NN);

    // fused persistent LSTM: 256 steps in one launch (time-major HS)
    lstm_persist<<<128, 256, LSTM_SMEM>>>(gXP, gWr, gHS);

    // K[t][b][:] = exp(HS[t][b][:] @ W_fc^T + b_fc)
    gemm128<2><<<dim3(2, 256, 1), 256>>>(
        gHS, LD, 0, (size_t)128 * LD,
        W_fc, LD, 0, b_fc, gK, NN, 0, LD);

    // Sinkhorn: 5 x (u = 1/(Kv); v = 1/(K^T u)), then combine
    for (int it = 0; it < 5; ++it) {
        sink_row<<<dim3(32, 128), 256>>>();
        sink_col<<<dim3(4, 128), 256>>>();
    }
    sink_out<<<dim3(256, 128), 256>>>(out);
}